// round 15
// baseline (speedup 1.0000x reference)
#include <cuda_runtime.h>
#include <math.h>

#define N 256
#define ND (N*N)
#define D 128
#define LAM 1e-3f
#define EPS 1e-3f

// ---- static scratch ----
__device__ float g_z2s[N*D];
__device__ float g_X[N*2*D], g_Xs[N*2*D];
__device__ float g_n1[N], g_n2[N], g_n2s[N], g_nX[N], g_nXs[N];
__device__ float g_Amat[8][ND];   // 0..3 denom A_s -> U (upper), 4..7 numerator
__device__ float g_Atr[8][ND];    // U^T rows (for backward solve)
__device__ float g_invd[8][N];
__device__ float g_Wm[4][ND];
__device__ float g_Mt[4][ND];     // row k = RHS column k of M_s
__device__ float g_bnumP[8][4][N];// partial row sums of exp(-c*DnB) per col-tile
__device__ float g_bnum[4][N];
__device__ float g_Csol[4][ND];   // row k = solution column k
__device__ float g_xnum[4][N];
__device__ float g_R[ND];
__device__ unsigned g_done = 0;

__constant__ float c_inv2s2[4] = {0.5f, 5.0e-3f, 5.0e-5f, 5.0e-7f};

// ---------- 1. gather + norms ----------
__global__ void k_gather(const float* __restrict__ z1, const float* __restrict__ z2,
                         const int* __restrict__ p1, const int* __restrict__ p2) {
    int i = blockIdx.x, t = threadIdx.x; // 128
    float a  = z1[i*D+t],      b  = z2[i*D+t];
    float as = z1[p1[i]*D+t],  bs = z2[p2[i]*D+t];
    g_X [i*2*D+t] = a;  g_X [i*2*D+D+t] = b;
    g_Xs[i*2*D+t] = as; g_Xs[i*2*D+D+t] = bs;
    g_z2s[i*D+t] = bs;
    float v1=a*a, v2=b*b, v3=as*as, v4=bs*bs;
    #pragma unroll
    for (int o=16;o;o>>=1){
        v1+=__shfl_down_sync(~0u,v1,o); v2+=__shfl_down_sync(~0u,v2,o);
        v3+=__shfl_down_sync(~0u,v3,o); v4+=__shfl_down_sync(~0u,v4,o);
    }
    __shared__ float s1[4],s2[4],s3[4],s4[4];
    int w=t>>5;
    if(!(t&31)){s1[w]=v1;s2[w]=v2;s3[w]=v3;s4[w]=v4;}
    __syncthreads();
    if(t==0){
        float n1=s1[0]+s1[1]+s1[2]+s1[3], n2=s2[0]+s2[1]+s2[2]+s2[3];
        float n1s=s3[0]+s3[1]+s3[2]+s3[3], n2s=s4[0]+s4[1]+s4[2]+s4[3];
        g_n1[i]=n1; g_n2[i]=n2; g_n2s[i]=n2s; g_nX[i]=n1+n2; g_nXs[i]=n1s+n2s;
    }
}

// ---------- 2. fused dist + build (5 mats via blockIdx.z) ----------
__global__ void k_distbuild(const float* __restrict__ z1, const float* __restrict__ z2) {
    const float *A,*B,*na,*nb; int K;
    int mat = blockIdx.z;
    switch (mat) {
        case 0:  A=z1;    B=z2;    na=g_n1;  nb=g_n2;  K=D;   break;
        case 1:  A=g_z2s; B=z2;    na=g_n2s; nb=g_n2;  K=D;   break;
        case 2:  A=g_z2s; B=g_z2s; na=g_n2s; nb=g_n2s; K=D;   break;
        case 3:  A=g_X;   B=g_X;   na=g_nX;  nb=g_nX;  K=2*D; break;
        default: A=g_X;   B=g_Xs;  na=g_nX;  nb=g_nXs; K=2*D; break;
    }
    __shared__ float As[32][33], Bs[32][33];
    int tx=threadIdx.x, ty=threadIdx.y;
    int rb=blockIdx.y*32, cb=blockIdx.x*32;
    int row=rb+ty, col=cb+tx;
    float acc=0.f;
    for (int kb=0; kb<K; kb+=32) {
        As[ty][tx]=A[row*K+kb+tx];
        Bs[ty][tx]=B[(cb+ty)*K+kb+tx];
        __syncthreads();
        #pragma unroll
        for (int kk=0; kk<32; kk++) acc=fmaf(As[ty][kk],Bs[tx][kk],acc);
        __syncthreads();
    }
    float dsq = fmaxf(na[row]+nb[col]-2.f*acc, 0.f);

    if (mat==0) {
        #pragma unroll
        for (int s=0;s<4;s++) g_Wm[s][row*N+col]=expf(-c_inv2s2[s]*dsq);
    } else if (mat==1) {
        // Mt[s][col*N+row] via smem transpose bounce (coalesced writes)
        for (int s=0;s<4;s++) {
            __syncthreads();
            As[ty][tx]=expf(-c_inv2s2[s]*dsq);
            __syncthreads();
            g_Mt[s][(cb+ty)*N + rb+tx] = As[tx][ty];
        }
    } else if (mat==2) {
        float lam_d=(row==col)?LAM:0.f;
        #pragma unroll
        for (int s=0;s<4;s++) g_Amat[s][row*N+col]=expf(-c_inv2s2[s]*dsq)+lam_d;
    } else if (mat==3) {
        float lam_d=(row==col)?LAM:0.f;
        #pragma unroll
        for (int s=0;s<4;s++) g_Amat[4+s][row*N+col]=expf(-c_inv2s2[s]*dsq)+lam_d;
    } else {
        // mat4: partial row sums; each warp = one row (lane=tx)
        #pragma unroll
        for (int s=0;s<4;s++) {
            float e=expf(-c_inv2s2[s]*dsq);
            #pragma unroll
            for (int o=16;o;o>>=1) e+=__shfl_down_sync(~0u,e,o);
            if (tx==0) g_bnumP[blockIdx.x][s][row]=e;
        }
    }
}

// ---------- 3. panel: rank-2 no-shfl 64x64 factor + fused off-diag TRSM + U^T write ----------
// Factor layout: thread (rg=t>>6, j=t&63) owns rows rg*16..+15 of column j in acc[16].
__global__ void __launch_bounds__(256) k_panel(int pb) {
    int m = blockIdx.x;
    float* A = g_Amat[m];
    float* At = g_Atr[m];
    __shared__ float Ubs[64][65];
    __shared__ float srow0[64], srow1[64];
    __shared__ float sinv[64];
    int t = threadIdx.x;
    int j = t & 63, rg = t >> 6, r0 = rg*16;

    if (pb==0 && m<4) {             // finalize numerator RHS (free threads, row t)
        float v=0.f;
        #pragma unroll
        for (int ct=0;ct<8;ct++) v += g_bnumP[ct][m][t];
        g_bnum[m][t]=v;
    }

    float acc[16];
    #pragma unroll
    for (int r=0;r<16;r++) acc[r] = A[(pb+r0+r)*N + pb + j];

    for (int k=0;k<64;k+=2) {
        __syncthreads();
        if (rg == (k>>4)) { srow0[j]=acc[k&15]; srow1[j]=acc[(k+1)&15]; }
        __syncthreads();
        float p0  = fmaxf(srow0[k], 1e-30f);
        float ip0 = 1.f/p0;
        float inv0= rsqrtf(p0);
        float a01 = srow0[k+1];
        float c01 = a01*ip0;
        float p1  = fmaxf(srow1[k+1] - a01*c01, 1e-30f);
        float ip1 = 1.f/p1;
        float inv1= rsqrtf(p1);
        float s0j = srow0[j]*ip0;
        float r1j = srow1[j] - srow0[j]*c01;
        float s1j = r1j*ip1;
        if (rg == (k>>4)) {
            acc[k&15]     = srow0[j]*inv0;
            acc[(k+1)&15] = r1j*inv1;
            if (j==k)   sinv[k]  =inv0;
            if (j==k+1) sinv[k+1]=inv1;
        }
        #pragma unroll
        for (int q=0;q<4;q++){
            float4 a4 = *(const float4*)&srow0[r0+4*q];
            float4 b4 = *(const float4*)&srow1[r0+4*q];
            float av[4]={a4.x,a4.y,a4.z,a4.w};
            float bv[4]={b4.x,b4.y,b4.z,b4.w};
            #pragma unroll
            for (int e=0;e<4;e++){
                int row = r0+4*q+e;
                if (row > k+1) {
                    float r1i = bv[e] - av[e]*c01;
                    acc[4*q+e] = fmaf(-av[e], s0j, acc[4*q+e]);
                    acc[4*q+e] = fmaf(-r1i,  s1j, acc[4*q+e]);
                }
            }
        }
    }
    __syncthreads();
    // publish factored tile: smem + U + U^T diag tile
    #pragma unroll
    for (int r=0;r<16;r++) {
        Ubs[r0+r][j] = acc[r];
        A[(pb+r0+r)*N + pb + j] = acc[r];
        At[(pb+j)*N + pb + r0 + r] = acc[r];      // U^T[pb+j][pb+r0+r]
    }
    if (t < 64) g_invd[m][pb+t] = sinv[t];
    __syncthreads();

    // off-diag TRSM: U12 = U11^{-T} A12, thread per column (smem broadcast reads)
    int jj = pb + 64 + t;
    if (jj < N) {
        float x[64];
        #pragma unroll
        for (int i=0;i<64;i++) x[i]=A[(pb+i)*N + jj];
        #pragma unroll
        for (int k=0;k<64;k++) {
            x[k]*=sinv[k];
            #pragma unroll
            for (int i=k+1;i<64;i++) x[i]=fmaf(-Ubs[k][i],x[k],x[i]);
        }
        #pragma unroll
        for (int i=0;i<64;i++) {
            A[(pb+i)*N + jj]=x[i];
            At[jj*N + pb + i]=x[i];               // U^T[jj][pb+i], contiguous per thread
        }
    }
}

// ---------- 4. trailing syrk: A22 -= U12^T U12, full-chip ----------
__global__ void __launch_bounds__(256) k_syrk(int pb) {
    if ((int)blockIdx.y > (int)blockIdx.x) return;   // upper tiles only
    float* A = g_Amat[blockIdx.z];
    int i0 = pb + 64 + blockIdx.y*32, j0 = pb + 64 + blockIdx.x*32;
    __shared__ float Ua[64][33], Vb[64][33];
    int t=threadIdx.x, tx=t&15, ty=t>>4;
    int lr=t>>5, lc=t&31;
    #pragma unroll
    for (int i=0;i<64;i+=8) {
        Ua[lr+i][lc]=A[(pb+lr+i)*N + i0 + lc];
        Vb[lr+i][lc]=A[(pb+lr+i)*N + j0 + lc];
    }
    __syncthreads();
    float a00=0.f,a01=0.f,a10=0.f,a11=0.f;
    #pragma unroll
    for (int k=0;k<64;k++) {
        float w0=Ua[k][ty], w1=Ua[k][ty+16];
        float c0=Vb[k][tx], c1=Vb[k][tx+16];
        a00=fmaf(w0,c0,a00); a01=fmaf(w0,c1,a01);
        a10=fmaf(w1,c0,a10); a11=fmaf(w1,c1,a11);
    }
    A[(i0+ty   )*N + j0+tx   ] -= a00;
    A[(i0+ty   )*N + j0+tx+16] -= a01;
    A[(i0+ty+16)*N + j0+tx   ] -= a10;
    A[(i0+ty+16)*N + j0+tx+16] -= a11;
}

// ---------- 5. register-resident TRSM, warp per column, 4-deep prefetch ----------
__global__ void __launch_bounds__(256) k_trsm() {
    int s=blockIdx.y, t=threadIdx.x, wid=t>>5, lane=t&31;
    const float *U,*L,*invd,*src; float* dst;
    if (blockIdx.x<32) {
        int col=blockIdx.x*8+wid;
        U=g_Amat[s]; L=g_Atr[s]; invd=g_invd[s];
        src=&g_Mt[s][col*N]; dst=&g_Csol[s][col*N];
    } else {
        if (wid) return;
        U=g_Amat[4+s]; L=g_Atr[4+s]; invd=g_invd[4+s];
        src=g_bnum[s]; dst=g_xnum[s];
    }
    float x[8], iv[8];
    #pragma unroll
    for (int r=0;r<8;r++){ x[r]=src[r*32+lane]; iv[r]=invd[r*32+lane]; }

    float ub[4][8];
    #pragma unroll
    for (int q=0;q<4;q++)
        #pragma unroll
        for (int r=0;r<8;r++) ub[q][r]=U[q*N + r*32 + lane];

    #pragma unroll
    for (int kr=0;kr<8;kr++) {
        #pragma unroll 1
        for (int kl4=0; kl4<32; kl4+=4) {
            #pragma unroll
            for (int q=0;q<4;q++) {
                int kl = kl4 + q;
                int k  = kr*32 + kl;
                float v = x[kr]*iv[kr];
                float xk = __shfl_sync(~0u, v, kl);
                if (lane==kl) x[kr]=xk;
                #pragma unroll
                for (int r=kr;r<8;r++) {
                    bool act = (r>kr) || (lane>kl);
                    float nx = fmaf(-ub[q][r], xk, x[r]);
                    x[r] = act ? nx : x[r];
                }
                int kn = k+4;
                if (kn < N) {
                    #pragma unroll
                    for (int r=0;r<8;r++) ub[q][r] = U[kn*N + r*32 + lane];
                }
            }
        }
    }
    #pragma unroll
    for (int q=0;q<4;q++)
        #pragma unroll
        for (int r=0;r<8;r++) ub[q][r]=L[(N-4+q)*N + r*32 + lane];

    #pragma unroll
    for (int kr=7;kr>=0;kr--) {
        #pragma unroll 1
        for (int kl4=28; kl4>=0; kl4-=4) {
            #pragma unroll
            for (int q=3;q>=0;q--) {
                int kl = kl4 + q;
                int k  = kr*32 + kl;
                float v = x[kr]*iv[kr];
                float xk = __shfl_sync(~0u, v, kl);
                if (lane==kl) x[kr]=xk;
                #pragma unroll
                for (int r=0;r<=kr;r++) {
                    bool act = (r<kr) || (lane<kl);
                    float nx = fmaf(-ub[q][r], xk, x[r]);
                    x[r] = act ? nx : x[r];
                }
                int kn = k-4;
                if (kn >= 0) {
                    #pragma unroll
                    for (int r=0;r<8;r++) ub[q][r] = L[kn*N + r*32 + lane];
                }
            }
        }
    }
    #pragma unroll
    for (int r=0;r<8;r++) dst[r*32+lane] = x[r];
}

// ---------- 6. R = sum_s W_s C_s^T + last-block rowsum/loss ----------
__global__ void __launch_bounds__(256) k_gemmR(float* __restrict__ out) {
    __shared__ float Wa[32][33], Cb[32][33];
    __shared__ float sden[256];
    __shared__ int isLast;
    int t=threadIdx.x;
    int tx=t&15, ty=t>>4;
    int rb=blockIdx.y*32, cb=blockIdx.x*32;
    int lr=t>>5, lc=t&31;
    int wid=t>>5, lane=t&31;
    float a00=0.f,a01=0.f,a10=0.f,a11=0.f;
    for (int s=0;s<4;s++) {
        const float* Wp=g_Wm[s]; const float* Cp=g_Csol[s];
        for (int kb=0;kb<N;kb+=32) {
            __syncthreads();
            #pragma unroll
            for(int i=0;i<32;i+=8){
                Wa[lr+i][lc]=Wp[(rb+lr+i)*N+kb+lc];
                Cb[lr+i][lc]=Cp[(cb+lr+i)*N+kb+lc];
            }
            __syncthreads();
            #pragma unroll
            for (int kk=0;kk<32;kk++) {
                float w0=Wa[ty][kk], w1=Wa[ty+16][kk];
                float c0=Cb[tx][kk], c1=Cb[tx+16][kk];
                a00=fmaf(w0,c0,a00); a01=fmaf(w0,c1,a01);
                a10=fmaf(w1,c0,a10); a11=fmaf(w1,c1,a11);
            }
        }
    }
    g_R[(rb+ty   )*N+cb+tx   ]=a00;
    g_R[(rb+ty   )*N+cb+tx+16]=a01;
    g_R[(rb+ty+16)*N+cb+tx   ]=a10;
    g_R[(rb+ty+16)*N+cb+tx+16]=a11;

    __threadfence();
    __syncthreads();
    if (t==0) { unsigned o=atomicAdd(&g_done,1u); isLast=(o==63u); }
    __syncthreads();
    if (!isLast) return;
    __threadfence();

    for (int r=wid*32; r<wid*32+32; r++) {
        float v=0.f;
        #pragma unroll
        for (int q=0;q<8;q++) v += fmaxf(g_R[r*N + q*32 + lane], 0.f);
        #pragma unroll
        for (int o=16;o;o>>=1) v += __shfl_down_sync(~0u,v,o);
        if (!lane) sden[r]=v;
    }
    __syncthreads();
    float est=fmaxf(0.25f*(g_xnum[0][t]+g_xnum[1][t]+g_xnum[2][t]+g_xnum[3][t]),0.f)+EPS;
    float v=logf(0.25f*sden[t]+(float)N*EPS)+logf(est);
    #pragma unroll
    for (int o=16;o;o>>=1) v += __shfl_down_sync(~0u,v,o);
    if(!lane) sden[wid]=v;
    __syncthreads();
    if (t==0) {
        float s0=0.f;
        #pragma unroll
        for (int w=0;w<8;w++) s0+=sden[w];
        out[0]=s0;
        g_done=0;            // reset for next replay
    }
}

extern "C" void kernel_launch(void* const* d_in, const int* in_sizes, int n_in,
                              void* d_out, int out_size) {
    const float* z1=(const float*)d_in[0];
    const float* z2=(const float*)d_in[1];
    const int*   p1=(const int*)d_in[2];
    const int*   p2=(const int*)d_in[3];
    float* out=(float*)d_out;

    k_gather<<<N,128>>>(z1,z2,p1,p2);
    k_distbuild<<<dim3(8,8,5),dim3(32,32)>>>(z1,z2);

    k_panel<<<8,256>>>(0);
    k_syrk<<<dim3(6,6,8),256>>>(0);
    k_panel<<<8,256>>>(64);
    k_syrk<<<dim3(4,4,8),256>>>(64);
    k_panel<<<8,256>>>(128);
    k_syrk<<<dim3(2,2,8),256>>>(128);
    k_panel<<<8,256>>>(192);

    k_trsm<<<dim3(33,4),256>>>();
    k_gemmR<<<dim3(8,8),256>>>(out);
}

// round 16
// speedup vs baseline: 1.1645x; 1.1645x over previous
#include <cuda_runtime.h>
#include <math.h>

#define N 256
#define ND (N*N)
#define D 128
#define LAM 1e-3f
#define EPS 1e-3f

// ---- static scratch ----
__device__ float g_z2s[N*D];
__device__ float g_X[N*2*D], g_Xs[N*2*D];
__device__ float g_n1[N], g_n2[N], g_n2s[N], g_nX[N], g_nXs[N];
__device__ float g_D1[ND], g_Dd[ND], g_Ddd[ND], g_DnA[ND], g_DnB[ND];
__device__ float g_Amat[8][ND];   // 0..3 denom A_s -> U (upper), 4..7 numerator
__device__ float g_Atr[8][ND];    // U^T rows (for backward solve)
__device__ float g_invd[8][N];
__device__ float g_Wm[4][ND];
__device__ float g_Mt[4][ND];     // row k = RHS column k of M_s
__device__ float g_bnum[4][N];
__device__ float g_Csol[4][ND];   // row k = solution column k
__device__ float g_xnum[4][N];
__device__ float g_R[ND];
__device__ float g_denum[N];

__constant__ float c_inv2s2[4] = {0.5f, 5.0e-3f, 5.0e-5f, 5.0e-7f};

// ---------- 1. gather + norms ----------
__global__ void k_gather(const float* __restrict__ z1, const float* __restrict__ z2,
                         const int* __restrict__ p1, const int* __restrict__ p2) {
    int i = blockIdx.x, t = threadIdx.x; // 128
    float a  = z1[i*D+t],      b  = z2[i*D+t];
    float as = z1[p1[i]*D+t],  bs = z2[p2[i]*D+t];
    g_X [i*2*D+t] = a;  g_X [i*2*D+D+t] = b;
    g_Xs[i*2*D+t] = as; g_Xs[i*2*D+D+t] = bs;
    g_z2s[i*D+t] = bs;
    float v1=a*a, v2=b*b, v3=as*as, v4=bs*bs;
    #pragma unroll
    for (int o=16;o;o>>=1){
        v1+=__shfl_down_sync(~0u,v1,o); v2+=__shfl_down_sync(~0u,v2,o);
        v3+=__shfl_down_sync(~0u,v3,o); v4+=__shfl_down_sync(~0u,v4,o);
    }
    __shared__ float s1[4],s2[4],s3[4],s4[4];
    int w=t>>5;
    if(!(t&31)){s1[w]=v1;s2[w]=v2;s3[w]=v3;s4[w]=v4;}
    __syncthreads();
    if(t==0){
        float n1=s1[0]+s1[1]+s1[2]+s1[3], n2=s2[0]+s2[1]+s2[2]+s2[3];
        float n1s=s3[0]+s3[1]+s3[2]+s3[3], n2s=s4[0]+s4[1]+s4[2]+s4[3];
        g_n1[i]=n1; g_n2[i]=n2; g_n2s[i]=n2s; g_nX[i]=n1+n2; g_nXs[i]=n1s+n2s;
    }
}

// ---------- 2. five squared-distance matrices ----------
__global__ void k_dist(const float* __restrict__ z1, const float* __restrict__ z2) {
    const float *A,*B,*na,*nb; float* out; int K;
    switch (blockIdx.z) {
        case 0:  A=z1;    B=z2;    na=g_n1;  nb=g_n2;  K=D;   out=g_D1;  break;
        case 1:  A=g_z2s; B=z2;    na=g_n2s; nb=g_n2;  K=D;   out=g_Dd;  break;
        case 2:  A=g_z2s; B=g_z2s; na=g_n2s; nb=g_n2s; K=D;   out=g_Ddd; break;
        case 3:  A=g_X;   B=g_X;   na=g_nX;  nb=g_nX;  K=2*D; out=g_DnA; break;
        default: A=g_X;   B=g_Xs;  na=g_nX;  nb=g_nXs; K=2*D; out=g_DnB; break;
    }
    __shared__ float As[32][33], Bs[32][33];
    int tx=threadIdx.x, ty=threadIdx.y;
    int row=blockIdx.y*32+ty, col=blockIdx.x*32+tx;
    float acc=0.f;
    for (int kb=0; kb<K; kb+=32) {
        As[ty][tx]=A[row*K+kb+tx];
        Bs[ty][tx]=B[(blockIdx.x*32+ty)*K+kb+tx];
        __syncthreads();
        #pragma unroll
        for (int kk=0; kk<32; kk++) acc=fmaf(As[ty][kk],Bs[tx][kk],acc);
        __syncthreads();
    }
    out[row*N+col]=fmaxf(na[row]+nb[col]-2.f*acc,0.f);
}

// ---------- 3. kernel matrices ----------
__global__ void k_build() {
    int r=blockIdx.x, s=blockIdx.y, t=threadIdx.x;  // block 256
    float c=c_inv2s2[s];
    float lam_d=(t==r)?LAM:0.f;
    g_Amat[s  ][r*N+t]=expf(-c*g_Ddd[r*N+t])+lam_d;
    g_Amat[4+s][r*N+t]=expf(-c*g_DnA[r*N+t])+lam_d;
    g_Wm[s][r*N+t]=expf(-c*g_D1[r*N+t]);
    g_Mt[s][t*N+r]=expf(-c*g_Dd[r*N+t]);
    float e=expf(-c*g_DnB[r*N+t]);
    #pragma unroll
    for (int o=16;o;o>>=1) e+=__shfl_down_sync(~0u,e,o);
    __shared__ float sr[8];
    if(!(t&31)) sr[t>>5]=e;
    __syncthreads();
    if(t==0){ float s0=0.f;
        #pragma unroll
        for(int w=0;w<8;w++) s0+=sr[w];
        g_bnum[s][r]=s0; }
}

// ---------- 4a. panel: rank-2 no-shfl 64x64 factor (512 thr) + fused off-diag TRSM ----------
// Factor layout: thread (rg=t>>6, j=t&63) owns rows rg*8..+7 of column j in acc[8].
__global__ void __launch_bounds__(512) k_panel(int pb) {
    int m = blockIdx.x;
    float* A = g_Amat[m];
    __shared__ float Ubs[64][65];
    __shared__ float srow0[64], srow1[64];
    __shared__ float sinv[64];
    int t = threadIdx.x;
    int j = t & 63, rg = t >> 6, r0 = rg*8;

    float acc[8];
    #pragma unroll
    for (int r=0;r<8;r++) acc[r] = A[(pb+r0+r)*N + pb + j];

    for (int k=0;k<64;k+=2) {                 // k even: rows k,k+1 share owner group
        __syncthreads();
        if (rg == (k>>3)) { srow0[j]=acc[k&7]; srow1[j]=acc[(k+1)&7]; }
        __syncthreads();
        float p0  = fmaxf(srow0[k], 1e-30f);
        float ip0 = 1.f/p0;
        float inv0= rsqrtf(p0);
        float a01 = srow0[k+1];
        float c01 = a01*ip0;
        float p1  = fmaxf(srow1[k+1] - a01*c01, 1e-30f);
        float ip1 = 1.f/p1;
        float inv1= rsqrtf(p1);
        float s0j = srow0[j]*ip0;
        float r1j = srow1[j] - srow0[j]*c01;   // corrected raw row k+1
        float s1j = r1j*ip1;
        if (rg == (k>>3)) {
            acc[k&7]     = srow0[j]*inv0;
            acc[(k+1)&7] = r1j*inv1;
            if (j==k)   sinv[k]  =inv0;
            if (j==k+1) sinv[k+1]=inv1;
        }
        #pragma unroll
        for (int q=0;q<2;q++){
            float4 a4 = *(const float4*)&srow0[r0+4*q];
            float4 b4 = *(const float4*)&srow1[r0+4*q];
            float av[4]={a4.x,a4.y,a4.z,a4.w};
            float bv[4]={b4.x,b4.y,b4.z,b4.w};
            #pragma unroll
            for (int e=0;e<4;e++){
                int row = r0+4*q+e;
                if (row > k+1) {
                    float r1i = bv[e] - av[e]*c01;
                    acc[4*q+e] = fmaf(-av[e], s0j, acc[4*q+e]);
                    acc[4*q+e] = fmaf(-r1i,  s1j, acc[4*q+e]);
                }
            }
        }
    }
    __syncthreads();
    // publish factored tile to smem + global, invd
    #pragma unroll
    for (int r=0;r<8;r++) {
        Ubs[r0+r][j] = acc[r];
        A[(pb+r0+r)*N + pb + j] = acc[r];
    }
    if (t < 64) g_invd[m][pb+t] = sinv[t];
    __syncthreads();

    // off-diag TRSM: U12 = U11^{-T} A12, thread per column (R8 verbatim)
    int jj = pb + 64 + t;
    if (jj < N) {
        float x[64];
        #pragma unroll
        for (int i=0;i<64;i++) x[i]=A[(pb+i)*N + jj];
        #pragma unroll
        for (int k=0;k<64;k++) {
            x[k]*=sinv[k];
            #pragma unroll
            for (int i=k+1;i<64;i++) x[i]=fmaf(-Ubs[k][i],x[k],x[i]);
        }
        #pragma unroll
        for (int i=0;i<64;i++) A[(pb+i)*N + jj]=x[i];
    }
}

// ---------- 4b. trailing syrk: A22 -= U12^T U12, full-chip ----------
__global__ void __launch_bounds__(256) k_syrk(int pb) {
    if ((int)blockIdx.y > (int)blockIdx.x) return;   // upper tiles only
    float* A = g_Amat[blockIdx.z];
    int i0 = pb + 64 + blockIdx.y*32, j0 = pb + 64 + blockIdx.x*32;
    __shared__ float Ua[64][33], Vb[64][33];
    int t=threadIdx.x, tx=t&15, ty=t>>4;
    int lr=t>>5, lc=t&31;
    #pragma unroll
    for (int i=0;i<64;i+=8) {
        Ua[lr+i][lc]=A[(pb+lr+i)*N + i0 + lc];
        Vb[lr+i][lc]=A[(pb+lr+i)*N + j0 + lc];
    }
    __syncthreads();
    float a00=0.f,a01=0.f,a10=0.f,a11=0.f;
    #pragma unroll
    for (int k=0;k<64;k++) {
        float w0=Ua[k][ty], w1=Ua[k][ty+16];
        float c0=Vb[k][tx], c1=Vb[k][tx+16];
        a00=fmaf(w0,c0,a00); a01=fmaf(w0,c1,a01);
        a10=fmaf(w1,c0,a10); a11=fmaf(w1,c1,a11);
    }
    A[(i0+ty   )*N + j0+tx   ] -= a00;
    A[(i0+ty   )*N + j0+tx+16] -= a01;
    A[(i0+ty+16)*N + j0+tx   ] -= a10;
    A[(i0+ty+16)*N + j0+tx+16] -= a11;
}

// ---------- 5. transpose U ----------
__global__ void k_transpose() {
    __shared__ float tile[32][33];
    const float* A=g_Amat[blockIdx.z]; float* At=g_Atr[blockIdx.z];
    int tx=threadIdx.x, ty=threadIdx.y;              // (32,8)
    int x0=blockIdx.x*32, y0=blockIdx.y*32;
    #pragma unroll
    for(int i=0;i<32;i+=8) tile[ty+i][tx]=A[(y0+ty+i)*N+x0+tx];
    __syncthreads();
    #pragma unroll
    for(int i=0;i<32;i+=8) At[(x0+ty+i)*N+y0+tx]=tile[tx][ty+i];
}

// ---------- 6. register-resident TRSM, warp per column, 4-deep prefetch ----------
__global__ void __launch_bounds__(256) k_trsm() {
    int s=blockIdx.y, t=threadIdx.x, wid=t>>5, lane=t&31;
    const float *U,*L,*invd,*src; float* dst;
    if (blockIdx.x<32) {
        int col=blockIdx.x*8+wid;
        U=g_Amat[s]; L=g_Atr[s]; invd=g_invd[s];
        src=&g_Mt[s][col*N]; dst=&g_Csol[s][col*N];
    } else {
        if (wid) return;
        U=g_Amat[4+s]; L=g_Atr[4+s]; invd=g_invd[4+s];
        src=g_bnum[s]; dst=g_xnum[s];
    }
    float x[8], iv[8];
    #pragma unroll
    for (int r=0;r<8;r++){ x[r]=src[r*32+lane]; iv[r]=invd[r*32+lane]; }

    float ub[4][8];
    #pragma unroll
    for (int q=0;q<4;q++)
        #pragma unroll
        for (int r=0;r<8;r++) ub[q][r]=U[q*N + r*32 + lane];

    #pragma unroll
    for (int kr=0;kr<8;kr++) {
        #pragma unroll 1
        for (int kl4=0; kl4<32; kl4+=4) {
            #pragma unroll
            for (int q=0;q<4;q++) {
                int kl = kl4 + q;
                int k  = kr*32 + kl;
                float v = x[kr]*iv[kr];
                float xk = __shfl_sync(~0u, v, kl);
                if (lane==kl) x[kr]=xk;
                #pragma unroll
                for (int r=kr;r<8;r++) {
                    bool act = (r>kr) || (lane>kl);
                    float nx = fmaf(-ub[q][r], xk, x[r]);
                    x[r] = act ? nx : x[r];
                }
                int kn = k+4;
                if (kn < N) {
                    #pragma unroll
                    for (int r=0;r<8;r++) ub[q][r] = U[kn*N + r*32 + lane];
                }
            }
        }
    }
    #pragma unroll
    for (int q=0;q<4;q++)
        #pragma unroll
        for (int r=0;r<8;r++) ub[q][r]=L[(N-4+q)*N + r*32 + lane];

    #pragma unroll
    for (int kr=7;kr>=0;kr--) {
        #pragma unroll 1
        for (int kl4=28; kl4>=0; kl4-=4) {
            #pragma unroll
            for (int q=3;q>=0;q--) {
                int kl = kl4 + q;
                int k  = kr*32 + kl;
                float v = x[kr]*iv[kr];
                float xk = __shfl_sync(~0u, v, kl);
                if (lane==kl) x[kr]=xk;
                #pragma unroll
                for (int r=0;r<=kr;r++) {
                    bool act = (r<kr) || (lane<kl);
                    float nx = fmaf(-ub[q][r], xk, x[r]);
                    x[r] = act ? nx : x[r];
                }
                int kn = k-4;
                if (kn >= 0) {
                    #pragma unroll
                    for (int r=0;r<8;r++) ub[q][r] = L[kn*N + r*32 + lane];
                }
            }
        }
    }
    #pragma unroll
    for (int r=0;r<8;r++) dst[r*32+lane] = x[r];
}

// ---------- 7. R = sum_s W_s * C_s^T ----------
__global__ void k_gemmR() {
    __shared__ float Wa[32][33], Cb[32][33];
    int t=threadIdx.x;                                // 256
    int tx=t&15, ty=t>>4;
    int rb=blockIdx.y*32, cb=blockIdx.x*32;
    int lr=t>>5, lc=t&31;
    float a00=0.f,a01=0.f,a10=0.f,a11=0.f;
    for (int s=0;s<4;s++) {
        const float* Wp=g_Wm[s]; const float* Cp=g_Csol[s];
        for (int kb=0;kb<N;kb+=32) {
            __syncthreads();
            #pragma unroll
            for(int i=0;i<32;i+=8){
                Wa[lr+i][lc]=Wp[(rb+lr+i)*N+kb+lc];
                Cb[lr+i][lc]=Cp[(cb+lr+i)*N+kb+lc];
            }
            __syncthreads();
            #pragma unroll
            for (int kk=0;kk<32;kk++) {
                float w0=Wa[ty][kk], w1=Wa[ty+16][kk];
                float c0=Cb[tx][kk], c1=Cb[tx+16][kk];
                a00=fmaf(w0,c0,a00); a01=fmaf(w0,c1,a01);
                a10=fmaf(w1,c0,a10); a11=fmaf(w1,c1,a11);
            }
        }
    }
    g_R[(rb+ty   )*N+cb+tx   ]=a00;
    g_R[(rb+ty   )*N+cb+tx+16]=a01;
    g_R[(rb+ty+16)*N+cb+tx   ]=a10;
    g_R[(rb+ty+16)*N+cb+tx+16]=a11;
}

// ---------- 8. row sums ----------
__global__ void k_rowsum() {
    int i=blockIdx.x, t=threadIdx.x;
    float v=fmaxf(g_R[i*N+t],0.f);
    #pragma unroll
    for(int o=16;o;o>>=1) v+=__shfl_down_sync(~0u,v,o);
    __shared__ float sr[8];
    if(!(t&31)) sr[t>>5]=v;
    __syncthreads();
    if(t==0){ float s0=0.f;
        #pragma unroll
        for(int w=0;w<8;w++) s0+=sr[w];
        g_denum[i]=0.25f*s0+(float)N*EPS; }
}

// ---------- 9. loss ----------
__global__ void k_loss(float* __restrict__ out) {
    int t=threadIdx.x;
    float est=fmaxf(0.25f*(g_xnum[0][t]+g_xnum[1][t]+g_xnum[2][t]+g_xnum[3][t]),0.f)+EPS;
    float v=logf(g_denum[t])+logf(est);
    #pragma unroll
    for(int o=16;o;o>>=1) v+=__shfl_down_sync(~0u,v,o);
    __shared__ float sr[8];
    if(!(t&31)) sr[t>>5]=v;
    __syncthreads();
    if(t==0){ float s0=0.f;
        #pragma unroll
        for(int w=0;w<8;w++) s0+=sr[w];
        out[0]=s0; }
}

extern "C" void kernel_launch(void* const* d_in, const int* in_sizes, int n_in,
                              void* d_out, int out_size) {
    const float* z1=(const float*)d_in[0];
    const float* z2=(const float*)d_in[1];
    const int*   p1=(const int*)d_in[2];
    const int*   p2=(const int*)d_in[3];
    float* out=(float*)d_out;

    k_gather<<<N,128>>>(z1,z2,p1,p2);
    k_dist<<<dim3(8,8,5),dim3(32,32)>>>(z1,z2);
    k_build<<<dim3(N,4),N>>>();

    k_panel<<<8,512>>>(0);
    k_syrk<<<dim3(6,6,8),256>>>(0);
    k_panel<<<8,512>>>(64);
    k_syrk<<<dim3(4,4,8),256>>>(64);
    k_panel<<<8,512>>>(128);
    k_syrk<<<dim3(2,2,8),256>>>(128);
    k_panel<<<8,512>>>(192);

    k_transpose<<<dim3(8,8,8),dim3(32,8)>>>();
    k_trsm<<<dim3(33,4),256>>>();
    k_gemmR<<<dim3(8,8),256>>>();
    k_rowsum<<<N,N>>>();
    k_loss<<<1,N>>>(out);
}

// round 17
// speedup vs baseline: 1.2140x; 1.0426x over previous
#include <cuda_runtime.h>
#include <math.h>

#define N 256
#define ND (N*N)
#define D 128
#define LAM 1e-3f
#define EPS 1e-3f

// ---- static scratch ----
__device__ float g_z2s[N*D];
__device__ float g_X[N*2*D], g_Xs[N*2*D];
__device__ float g_n1[N], g_n2[N], g_n2s[N], g_nX[N], g_nXs[N];
__device__ float g_D1[ND], g_Dd[ND], g_Ddd[ND], g_DnA[ND], g_DnB[ND];
__device__ float g_Amat[8][ND];   // 0..3 denom A_s -> U (upper), 4..7 numerator
__device__ float g_Atr[8][ND];    // U^T rows (for backward solve)
__device__ float g_invd[8][N];
__device__ float g_Wm[4][ND];
__device__ float g_Mt[4][ND];     // row k = RHS column k of M_s
__device__ float g_bnum[4][N];
__device__ float g_Csol[4][ND];   // row k = solution column k
__device__ float g_xnum[4][N];
__device__ float g_R[ND];
__device__ float g_denum[N];

__constant__ float c_inv2s2[4] = {0.5f, 5.0e-3f, 5.0e-5f, 5.0e-7f};

// ---------- 1. gather + norms ----------
__global__ void k_gather(const float* __restrict__ z1, const float* __restrict__ z2,
                         const int* __restrict__ p1, const int* __restrict__ p2) {
    int i = blockIdx.x, t = threadIdx.x; // 128
    float a  = z1[i*D+t],      b  = z2[i*D+t];
    float as = z1[p1[i]*D+t],  bs = z2[p2[i]*D+t];
    g_X [i*2*D+t] = a;  g_X [i*2*D+D+t] = b;
    g_Xs[i*2*D+t] = as; g_Xs[i*2*D+D+t] = bs;
    g_z2s[i*D+t] = bs;
    float v1=a*a, v2=b*b, v3=as*as, v4=bs*bs;
    #pragma unroll
    for (int o=16;o;o>>=1){
        v1+=__shfl_down_sync(~0u,v1,o); v2+=__shfl_down_sync(~0u,v2,o);
        v3+=__shfl_down_sync(~0u,v3,o); v4+=__shfl_down_sync(~0u,v4,o);
    }
    __shared__ float s1[4],s2[4],s3[4],s4[4];
    int w=t>>5;
    if(!(t&31)){s1[w]=v1;s2[w]=v2;s3[w]=v3;s4[w]=v4;}
    __syncthreads();
    if(t==0){
        float n1=s1[0]+s1[1]+s1[2]+s1[3], n2=s2[0]+s2[1]+s2[2]+s2[3];
        float n1s=s3[0]+s3[1]+s3[2]+s3[3], n2s=s4[0]+s4[1]+s4[2]+s4[3];
        g_n1[i]=n1; g_n2[i]=n2; g_n2s[i]=n2s; g_nX[i]=n1+n2; g_nXs[i]=n1s+n2s;
    }
}

// ---------- 2. five squared-distance matrices ----------
__global__ void k_dist(const float* __restrict__ z1, const float* __restrict__ z2) {
    const float *A,*B,*na,*nb; float* out; int K;
    switch (blockIdx.z) {
        case 0:  A=z1;    B=z2;    na=g_n1;  nb=g_n2;  K=D;   out=g_D1;  break;
        case 1:  A=g_z2s; B=z2;    na=g_n2s; nb=g_n2;  K=D;   out=g_Dd;  break;
        case 2:  A=g_z2s; B=g_z2s; na=g_n2s; nb=g_n2s; K=D;   out=g_Ddd; break;
        case 3:  A=g_X;   B=g_X;   na=g_nX;  nb=g_nX;  K=2*D; out=g_DnA; break;
        default: A=g_X;   B=g_Xs;  na=g_nX;  nb=g_nXs; K=2*D; out=g_DnB; break;
    }
    __shared__ float As[32][33], Bs[32][33];
    int tx=threadIdx.x, ty=threadIdx.y;
    int row=blockIdx.y*32+ty, col=blockIdx.x*32+tx;
    float acc=0.f;
    for (int kb=0; kb<K; kb+=32) {
        As[ty][tx]=A[row*K+kb+tx];
        Bs[ty][tx]=B[(blockIdx.x*32+ty)*K+kb+tx];
        __syncthreads();
        #pragma unroll
        for (int kk=0; kk<32; kk++) acc=fmaf(As[ty][kk],Bs[tx][kk],acc);
        __syncthreads();
    }
    out[row*N+col]=fmaxf(na[row]+nb[col]-2.f*acc,0.f);
}

// ---------- 3. kernel matrices ----------
__global__ void k_build() {
    int r=blockIdx.x, s=blockIdx.y, t=threadIdx.x;  // block 256
    float c=c_inv2s2[s];
    float lam_d=(t==r)?LAM:0.f;
    g_Amat[s  ][r*N+t]=expf(-c*g_Ddd[r*N+t])+lam_d;
    g_Amat[4+s][r*N+t]=expf(-c*g_DnA[r*N+t])+lam_d;
    g_Wm[s][r*N+t]=expf(-c*g_D1[r*N+t]);
    g_Mt[s][t*N+r]=expf(-c*g_Dd[r*N+t]);
    float e=expf(-c*g_DnB[r*N+t]);
    #pragma unroll
    for (int o=16;o;o>>=1) e+=__shfl_down_sync(~0u,e,o);
    __shared__ float sr[8];
    if(!(t&31)) sr[t>>5]=e;
    __syncthreads();
    if(t==0){ float s0=0.f;
        #pragma unroll
        for(int w=0;w<8;w++) s0+=sr[w];
        g_bnum[s][r]=s0; }
}

// ---------- 4a. panel: rank-2 no-shfl 64x64 factor (512 thr) + fused off-diag TRSM ----------
// Factor layout: thread (rg=t>>6, j=t&63) owns rows rg*8..+7 of column j in acc[8].
__global__ void __launch_bounds__(512) k_panel(int pb) {
    int m = blockIdx.x;
    float* A = g_Amat[m];
    __shared__ float Ubs[64][65];
    __shared__ float srow0[64], srow1[64];
    __shared__ float sinv[64];
    int t = threadIdx.x;
    int j = t & 63, rg = t >> 6, r0 = rg*8;

    float acc[8];
    #pragma unroll
    for (int r=0;r<8;r++) acc[r] = A[(pb+r0+r)*N + pb + j];

    for (int k=0;k<64;k+=2) {                 // k even: rows k,k+1 share owner group
        __syncthreads();
        if (rg == (k>>3)) { srow0[j]=acc[k&7]; srow1[j]=acc[(k+1)&7]; }
        __syncthreads();
        float p0  = fmaxf(srow0[k], 1e-30f);
        float ip0 = 1.f/p0;
        float inv0= rsqrtf(p0);
        float a01 = srow0[k+1];
        float c01 = a01*ip0;
        float p1  = fmaxf(srow1[k+1] - a01*c01, 1e-30f);
        float ip1 = 1.f/p1;
        float inv1= rsqrtf(p1);
        float s0j = srow0[j]*ip0;
        float r1j = srow1[j] - srow0[j]*c01;   // corrected raw row k+1
        float s1j = r1j*ip1;
        if (rg == (k>>3)) {
            acc[k&7]     = srow0[j]*inv0;
            acc[(k+1)&7] = r1j*inv1;
            if (j==k)   sinv[k]  =inv0;
            if (j==k+1) sinv[k+1]=inv1;
        }
        #pragma unroll
        for (int q=0;q<2;q++){
            float4 a4 = *(const float4*)&srow0[r0+4*q];
            float4 b4 = *(const float4*)&srow1[r0+4*q];
            float av[4]={a4.x,a4.y,a4.z,a4.w};
            float bv[4]={b4.x,b4.y,b4.z,b4.w};
            #pragma unroll
            for (int e=0;e<4;e++){
                int row = r0+4*q+e;
                if (row > k+1) {
                    float r1i = bv[e] - av[e]*c01;
                    acc[4*q+e] = fmaf(-av[e], s0j, acc[4*q+e]);
                    acc[4*q+e] = fmaf(-r1i,  s1j, acc[4*q+e]);
                }
            }
        }
    }
    __syncthreads();
    // publish factored tile to smem + global, invd
    #pragma unroll
    for (int r=0;r<8;r++) {
        Ubs[r0+r][j] = acc[r];
        A[(pb+r0+r)*N + pb + j] = acc[r];
    }
    if (t < 64) g_invd[m][pb+t] = sinv[t];
    __syncthreads();

    // off-diag TRSM: U12 = U11^{-T} A12, thread per column
    int jj = pb + 64 + t;
    if (jj < N) {
        float x[64];
        #pragma unroll
        for (int i=0;i<64;i++) x[i]=A[(pb+i)*N + jj];
        #pragma unroll
        for (int k=0;k<64;k++) {
            x[k]*=sinv[k];
            #pragma unroll
            for (int i=k+1;i<64;i++) x[i]=fmaf(-Ubs[k][i],x[k],x[i]);
        }
        #pragma unroll
        for (int i=0;i<64;i++) A[(pb+i)*N + jj]=x[i];
    }
}

// ---------- 4b. trailing syrk: A22 -= U12^T U12, full-chip ----------
__global__ void __launch_bounds__(256) k_syrk(int pb) {
    if ((int)blockIdx.y > (int)blockIdx.x) return;   // upper tiles only
    float* A = g_Amat[blockIdx.z];
    int i0 = pb + 64 + blockIdx.y*32, j0 = pb + 64 + blockIdx.x*32;
    __shared__ float Ua[64][33], Vb[64][33];
    int t=threadIdx.x, tx=t&15, ty=t>>4;
    int lr=t>>5, lc=t&31;
    #pragma unroll
    for (int i=0;i<64;i+=8) {
        Ua[lr+i][lc]=A[(pb+lr+i)*N + i0 + lc];
        Vb[lr+i][lc]=A[(pb+lr+i)*N + j0 + lc];
    }
    __syncthreads();
    float a00=0.f,a01=0.f,a10=0.f,a11=0.f;
    #pragma unroll
    for (int k=0;k<64;k++) {
        float w0=Ua[k][ty], w1=Ua[k][ty+16];
        float c0=Vb[k][tx], c1=Vb[k][tx+16];
        a00=fmaf(w0,c0,a00); a01=fmaf(w0,c1,a01);
        a10=fmaf(w1,c0,a10); a11=fmaf(w1,c1,a11);
    }
    A[(i0+ty   )*N + j0+tx   ] -= a00;
    A[(i0+ty   )*N + j0+tx+16] -= a01;
    A[(i0+ty+16)*N + j0+tx   ] -= a10;
    A[(i0+ty+16)*N + j0+tx+16] -= a11;
}

// ---------- 5. transpose U ----------
__global__ void k_transpose() {
    __shared__ float tile[32][33];
    const float* A=g_Amat[blockIdx.z]; float* At=g_Atr[blockIdx.z];
    int tx=threadIdx.x, ty=threadIdx.y;              // (32,8)
    int x0=blockIdx.x*32, y0=blockIdx.y*32;
    #pragma unroll
    for(int i=0;i<32;i+=8) tile[ty+i][tx]=A[(y0+ty+i)*N+x0+tx];
    __syncthreads();
    #pragma unroll
    for(int i=0;i<32;i+=8) At[(x0+ty+i)*N+y0+tx]=tile[tx][ty+i];
}

// ---------- 6. register-resident TRSM, warp per column, 8-deep prefetch ----------
__global__ void __launch_bounds__(256) k_trsm() {
    int s=blockIdx.y, t=threadIdx.x, wid=t>>5, lane=t&31;
    const float *U,*L,*invd,*src; float* dst;
    if (blockIdx.x<32) {
        int col=blockIdx.x*8+wid;
        U=g_Amat[s]; L=g_Atr[s]; invd=g_invd[s];
        src=&g_Mt[s][col*N]; dst=&g_Csol[s][col*N];
    } else {
        if (wid) return;
        U=g_Amat[4+s]; L=g_Atr[4+s]; invd=g_invd[4+s];
        src=g_bnum[s]; dst=g_xnum[s];
    }
    float x[8], iv[8];
    #pragma unroll
    for (int r=0;r<8;r++){ x[r]=src[r*32+lane]; iv[r]=invd[r*32+lane]; }

    float ub[8][8];
    // ---- forward: U^T y = b ----
    #pragma unroll
    for (int q=0;q<8;q++)
        #pragma unroll
        for (int r=0;r<8;r++) ub[q][r]=U[q*N + r*32 + lane];

    #pragma unroll
    for (int kr=0;kr<8;kr++) {
        #pragma unroll 1
        for (int kl8=0; kl8<32; kl8+=8) {
            #pragma unroll
            for (int q=0;q<8;q++) {
                int kl = kl8 + q;
                int k  = kr*32 + kl;
                float v = x[kr]*iv[kr];
                float xk = __shfl_sync(~0u, v, kl);
                if (lane==kl) x[kr]=xk;
                #pragma unroll
                for (int r=kr;r<8;r++) {
                    bool act = (r>kr) || (lane>kl);
                    float nx = fmaf(-ub[q][r], xk, x[r]);
                    x[r] = act ? nx : x[r];
                }
                int kn = k+8;
                if (kn < N) {
                    #pragma unroll
                    for (int r=0;r<8;r++) ub[q][r] = U[kn*N + r*32 + lane];
                }
            }
        }
    }
    // ---- backward: U x = y ----
    #pragma unroll
    for (int q=0;q<8;q++)
        #pragma unroll
        for (int r=0;r<8;r++) ub[q][r]=L[(N-8+q)*N + r*32 + lane];

    #pragma unroll
    for (int kr=7;kr>=0;kr--) {
        #pragma unroll 1
        for (int kl8=24; kl8>=0; kl8-=8) {
            #pragma unroll
            for (int q=7;q>=0;q--) {
                int kl = kl8 + q;
                int k  = kr*32 + kl;
                float v = x[kr]*iv[kr];
                float xk = __shfl_sync(~0u, v, kl);
                if (lane==kl) x[kr]=xk;
                #pragma unroll
                for (int r=0;r<=kr;r++) {
                    bool act = (r<kr) || (lane<kl);
                    float nx = fmaf(-ub[q][r], xk, x[r]);
                    x[r] = act ? nx : x[r];
                }
                int kn = k-8;
                if (kn >= 0) {
                    #pragma unroll
                    for (int r=0;r<8;r++) ub[q][r] = L[kn*N + r*32 + lane];
                }
            }
        }
    }
    #pragma unroll
    for (int r=0;r<8;r++) dst[r*32+lane] = x[r];
}

// ---------- 7. R = sum_s W_s * C_s^T ----------
__global__ void k_gemmR() {
    __shared__ float Wa[32][33], Cb[32][33];
    int t=threadIdx.x;                                // 256
    int tx=t&15, ty=t>>4;
    int rb=blockIdx.y*32, cb=blockIdx.x*32;
    int lr=t>>5, lc=t&31;
    float a00=0.f,a01=0.f,a10=0.f,a11=0.f;
    for (int s=0;s<4;s++) {
        const float* Wp=g_Wm[s]; const float* Cp=g_Csol[s];
        for (int kb=0;kb<N;kb+=32) {
            __syncthreads();
            #pragma unroll
            for(int i=0;i<32;i+=8){
                Wa[lr+i][lc]=Wp[(rb+lr+i)*N+kb+lc];
                Cb[lr+i][lc]=Cp[(cb+lr+i)*N+kb+lc];
            }
            __syncthreads();
            #pragma unroll
            for (int kk=0;kk<32;kk++) {
                float w0=Wa[ty][kk], w1=Wa[ty+16][kk];
                float c0=Cb[tx][kk], c1=Cb[tx+16][kk];
                a00=fmaf(w0,c0,a00); a01=fmaf(w0,c1,a01);
                a10=fmaf(w1,c0,a10); a11=fmaf(w1,c1,a11);
            }
        }
    }
    g_R[(rb+ty   )*N+cb+tx   ]=a00;
    g_R[(rb+ty   )*N+cb+tx+16]=a01;
    g_R[(rb+ty+16)*N+cb+tx   ]=a10;
    g_R[(rb+ty+16)*N+cb+tx+16]=a11;
}

// ---------- 8. row sums ----------
__global__ void k_rowsum() {
    int i=blockIdx.x, t=threadIdx.x;
    float v=fmaxf(g_R[i*N+t],0.f);
    #pragma unroll
    for(int o=16;o;o>>=1) v+=__shfl_down_sync(~0u,v,o);
    __shared__ float sr[8];
    if(!(t&31)) sr[t>>5]=v;
    __syncthreads();
    if(t==0){ float s0=0.f;
        #pragma unroll
        for(int w=0;w<8;w++) s0+=sr[w];
        g_denum[i]=0.25f*s0+(float)N*EPS; }
}

// ---------- 9. loss ----------
__global__ void k_loss(float* __restrict__ out) {
    int t=threadIdx.x;
    float est=fmaxf(0.25f*(g_xnum[0][t]+g_xnum[1][t]+g_xnum[2][t]+g_xnum[3][t]),0.f)+EPS;
    float v=logf(g_denum[t])+logf(est);
    #pragma unroll
    for(int o=16;o;o>>=1) v+=__shfl_down_sync(~0u,v,o);
    __shared__ float sr[8];
    if(!(t&31)) sr[t>>5]=v;
    __syncthreads();
    if(t==0){ float s0=0.f;
        #pragma unroll
        for(int w=0;w<8;w++) s0+=sr[w];
        out[0]=s0; }
}

extern "C" void kernel_launch(void* const* d_in, const int* in_sizes, int n_in,
                              void* d_out, int out_size) {
    const float* z1=(const float*)d_in[0];
    const float* z2=(const float*)d_in[1];
    const int*   p1=(const int*)d_in[2];
    const int*   p2=(const int*)d_in[3];
    float* out=(float*)d_out;

    k_gather<<<N,128>>>(z1,z2,p1,p2);
    k_dist<<<dim3(8,8,5),dim3(32,32)>>>(z1,z2);
    k_build<<<dim3(N,4),N>>>();

    k_panel<<<8,512>>>(0);
    k_syrk<<<dim3(6,6,8),256>>>(0);
    k_panel<<<8,512>>>(64);
    k_syrk<<<dim3(4,4,8),256>>>(64);
    k_panel<<<8,512>>>(128);
    k_syrk<<<dim3(2,2,8),256>>>(128);
    k_panel<<<8,512>>>(192);

    k_transpose<<<dim3(8,8,8),dim3(32,8)>>>();
    k_trsm<<<dim3(33,4),256>>>();
    k_gemmR<<<dim3(8,8),256>>>();
    k_rowsum<<<N,N>>>();
    k_loss<<<1,N>>>(out);
}